// round 4
// baseline (speedup 1.0000x reference)
#include <cuda_runtime.h>
#include <cuda_bf16.h>
#include <cuda_fp16.h>
#include <cstdint>
#include <math.h>

#define NP 8192
#define DIM 512

// ---------------- device scratch (statics: allowed, no runtime alloc) ----------
__device__ __nv_bfloat16 g_Xh[(size_t)NP * DIM];
__device__ __nv_bfloat16 g_Yh[(size_t)NP * DIM];
__device__ __half        g_G[(size_t)NP * NP];     // 128 MB
__device__ float         g_lu[NP], g_lv[NP], g_part[NP];

// ---------------- helpers -------------------------------------------------------
__device__ __forceinline__ uint32_t smem_u32(const void* p) {
    uint32_t a;
    asm("{ .reg .u64 t; cvta.to.shared.u64 t, %1; cvt.u32.u64 %0, t; }" : "=r"(a) : "l"(p));
    return a;
}
__device__ __forceinline__ void cp16(uint32_t s, const void* g) {
    asm volatile("cp.async.cg.shared.global [%0], [%1], 16;" :: "r"(s), "l"(g));
}
__device__ __forceinline__ void ldsm4(uint32_t& r0, uint32_t& r1, uint32_t& r2,
                                      uint32_t& r3, uint32_t a) {
    asm volatile("ldmatrix.sync.aligned.m8n8.x4.shared.b16 {%0,%1,%2,%3}, [%4];"
                 : "=r"(r0), "=r"(r1), "=r"(r2), "=r"(r3) : "r"(a));
}
__device__ __forceinline__ void mma16816(float* d, const uint32_t* a, const uint32_t* b) {
    asm volatile(
        "mma.sync.aligned.m16n8k16.row.col.f32.bf16.bf16.f32 "
        "{%0,%1,%2,%3}, {%4,%5,%6,%7}, {%8,%9}, {%0,%1,%2,%3};"
        : "+f"(d[0]), "+f"(d[1]), "+f"(d[2]), "+f"(d[3])
        : "r"(a[0]), "r"(a[1]), "r"(a[2]), "r"(a[3]), "r"(b[0]), "r"(b[1]));
}

// ---------------- 1) normalize: fp32 -> unit rows -> bf16 ----------------------
__global__ __launch_bounds__(128) void normalize_kernel(const float* __restrict__ x,
                                                        const float* __restrict__ y) {
    int b = blockIdx.x;
    const float* src = (b < NP) ? x : y;
    __nv_bfloat16* dst = (b < NP) ? g_Xh : g_Yh;
    int i = (b < NP) ? b : b - NP;
    int tid = threadIdx.x;

    float4 v = ((const float4*)(src + (size_t)i * DIM))[tid];
    float ss = v.x * v.x + v.y * v.y + v.z * v.z + v.w * v.w;
    __shared__ float red[128];
    red[tid] = ss;
    __syncthreads();
    for (int o = 64; o; o >>= 1) {
        if (tid < o) red[tid] += red[tid + o];
        __syncthreads();
    }
    float inv = 1.f / fmaxf(sqrtf(red[0]), 1e-12f);
    __nv_bfloat162* d2 = (__nv_bfloat162*)(dst + (size_t)i * DIM);
    d2[tid * 2]     = __floats2bfloat162_rn(v.x * inv, v.y * inv);
    d2[tid * 2 + 1] = __floats2bfloat162_rn(v.z * inv, v.w * inv);
}

// ---------------- 2) HMMA bf16 GEMM: G = Xh * Yh^T (fp16 out) -------------------
// CTA tile 128x64, BK=64, 2-stage cp.async pipeline, 48KB static smem.
// smem layout: A stages [0, 32768) (2 x 16KB), B stages [32768, 49152) (2 x 8KB).
// Rows are 128B (64 bf16), XOR-swizzled: chunk ^= (row & 7)  -> conflict-free LDSM.
#define BM 128
#define BN 64
#define BK 64
#define KITERS (DIM / BK)   // 8

__global__ __launch_bounds__(256) void gemm_kernel() {
    __shared__ __align__(1024) char sm[49152];
    uint32_t smb = smem_u32(sm);

    int tid = threadIdx.x;
    int lane = tid & 31;
    int w = tid >> 5;
    int warp_m = w & 3;        // 4 warps in M (32 rows each)
    int warp_n = w >> 2;       // 2 warps in N (32 cols each)
    int m0 = blockIdx.y * BM;
    int n0 = blockIdx.x * BN;

    auto load_stage = [&](int s, int kc) {
        // A: 128 rows x 8 chunks of 16B
        #pragma unroll
        for (int it = 0; it < 4; it++) {
            int idx = tid + it * 256;
            int row = idx >> 3, ch = idx & 7;
            const char* g = (const char*)(g_Xh + (size_t)(m0 + row) * DIM + kc) + ch * 16;
            cp16(smb + s * 16384 + row * 128 + ((ch ^ (row & 7)) << 4), g);
        }
        // B: 64 rows x 8 chunks
        #pragma unroll
        for (int it = 0; it < 2; it++) {
            int idx = tid + it * 256;
            int row = idx >> 3, ch = idx & 7;
            const char* g = (const char*)(g_Yh + (size_t)(n0 + row) * DIM + kc) + ch * 16;
            cp16(smb + 32768 + s * 8192 + row * 128 + ((ch ^ (row & 7)) << 4), g);
        }
        asm volatile("cp.async.commit_group;" ::: "memory");
    };

    float acc[2][4][4];
    #pragma unroll
    for (int mt = 0; mt < 2; mt++)
        #pragma unroll
        for (int nt = 0; nt < 4; nt++)
            #pragma unroll
            for (int q = 0; q < 4; q++) acc[mt][nt][q] = 0.f;

    load_stage(0, 0);
    load_stage(1, BK);

    for (int t = 0; t < KITERS; t++) {
        if (t < KITERS - 2)
            asm volatile("cp.async.wait_group 1;" ::: "memory");
        else
            asm volatile("cp.async.wait_group 0;" ::: "memory");
        __syncthreads();

        int s = t & 1;
        uint32_t aBase = smb + s * 16384;
        uint32_t bBase = smb + 32768 + s * 8192;

        #pragma unroll
        for (int ks = 0; ks < 4; ks++) {   // 4 k16 steps per BK=64
            uint32_t afr[2][4], bfr[4][2];
            #pragma unroll
            for (int mt = 0; mt < 2; mt++) {
                int row = warp_m * 32 + mt * 16 + (lane & 15);
                int ch = ks * 2 + (lane >> 4);
                ldsm4(afr[mt][0], afr[mt][1], afr[mt][2], afr[mt][3],
                      aBase + row * 128 + ((ch ^ (row & 7)) << 4));
            }
            #pragma unroll
            for (int nt2 = 0; nt2 < 2; nt2++) {
                int row = warp_n * 32 + nt2 * 16 + (lane & 15);
                int ch = ks * 2 + (lane >> 4);
                uint32_t r0, r1, r2, r3;
                ldsm4(r0, r1, r2, r3, bBase + row * 128 + ((ch ^ (row & 7)) << 4));
                bfr[nt2 * 2][0] = r0;     bfr[nt2 * 2][1] = r2;
                bfr[nt2 * 2 + 1][0] = r1; bfr[nt2 * 2 + 1][1] = r3;
            }
            #pragma unroll
            for (int mt = 0; mt < 2; mt++)
                #pragma unroll
                for (int nt = 0; nt < 4; nt++)
                    mma16816(acc[mt][nt], afr[mt], bfr[nt]);
        }
        __syncthreads();
        if (t + 2 < KITERS) load_stage(s, (t + 2) * BK);
    }

    // epilogue: fp16 stores
    int r0 = m0 + warp_m * 32 + (lane >> 2);
    int c0 = n0 + warp_n * 32 + (lane & 3) * 2;
    #pragma unroll
    for (int mt = 0; mt < 2; mt++)
        #pragma unroll
        for (int nt = 0; nt < 4; nt++) {
            int r = r0 + mt * 16;
            int c = c0 + nt * 8;
            *(__half2*)(g_G + (size_t)r * NP + c) =
                __floats2half2_rn(acc[mt][nt][0], acc[mt][nt][1]);
            *(__half2*)(g_G + (size_t)(r + 8) * NP + c) =
                __floats2half2_rn(acc[mt][nt][2], acc[mt][nt][3]);
        }
}

// ---------------- 3) init potentials -------------------------------------------
__global__ void init_kernel() {
    int i = blockIdx.x * blockDim.x + threadIdx.x;
    if (i < NP) { g_lu[i] = 0.f; g_lv[i] = 0.f; }
}

// logK_ij + t = -10*max(1-g,0) + t   (sq_x=sq_y=1 to ~1e-7; C = 2*max(1-g,0))
__device__ __forceinline__ void lse_step(float g, float t, float& m, float& s) {
    float c = fmaxf(1.f - g, 0.f);
    float v = fmaf(-10.f, c, t);
    if (v <= m) {
        s += __expf(v - m);
    } else {
        s = fmaf(s, __expf(m - v), 1.f);
        m = v;
    }
}

// ---------------- 4) row LSE: lu_i = -LSE_j(logK + lv_j) ------------------------
__global__ __launch_bounds__(256) void row_lse_kernel(const float* __restrict__ lvin,
                                                      float* __restrict__ luout) {
    __shared__ float s_v[NP];
    int tid = threadIdx.x;
    for (int j = tid * 4; j < NP; j += 1024)
        *(float4*)(s_v + j) = *(const float4*)(lvin + j);
    __syncthreads();
    int warp = tid >> 5, lane = tid & 31;
    #pragma unroll
    for (int rr = 0; rr < 2; rr++) {
        int i = blockIdx.x * 16 + warp * 2 + rr;
        const __half* row = g_G + (size_t)i * NP;
        float m = -1e30f, s = 0.f;
        for (int jb = lane * 8; jb < NP; jb += 256) {
            uint4 pk = *(const uint4*)(row + jb);
            float4 l0 = *(const float4*)(s_v + jb);
            float4 l1 = *(const float4*)(s_v + jb + 4);
            const __half2* hh = (const __half2*)&pk;
            float2 f0 = __half22float2(hh[0]);
            float2 f1 = __half22float2(hh[1]);
            float2 f2 = __half22float2(hh[2]);
            float2 f3 = __half22float2(hh[3]);
            lse_step(f0.x, l0.x, m, s); lse_step(f0.y, l0.y, m, s);
            lse_step(f1.x, l0.z, m, s); lse_step(f1.y, l0.w, m, s);
            lse_step(f2.x, l1.x, m, s); lse_step(f2.y, l1.y, m, s);
            lse_step(f3.x, l1.z, m, s); lse_step(f3.y, l1.w, m, s);
        }
        #pragma unroll
        for (int o = 16; o; o >>= 1) {
            float mo = __shfl_xor_sync(0xffffffffu, m, o);
            float so = __shfl_xor_sync(0xffffffffu, s, o);
            float nm = fmaxf(m, mo);
            s = s * __expf(m - nm) + so * __expf(mo - nm);
            m = nm;
        }
        if (lane == 0) luout[i] = -(m + __logf(s));
    }
}

// ---------------- 5) col LSE: lv_j = -LSE_i(logK + lu_i) ------------------------
__global__ __launch_bounds__(256) void col_lse_kernel(const float* __restrict__ luin,
                                                      float* __restrict__ lvout) {
    __shared__ float s_u[NP];
    __shared__ float rm[8][64], rs[8][64];
    int tid = threadIdx.x + threadIdx.y * 32;
    for (int j = tid * 4; j < NP; j += 1024)
        *(float4*)(s_u + j) = *(const float4*)(luin + j);
    __syncthreads();
    int tx = threadIdx.x, ty = threadIdx.y;
    int col = blockIdx.x * 64 + tx * 2;
    float m0 = -1e30f, s0 = 0.f, m1 = -1e30f, s1 = 0.f;
    for (int i = ty; i < NP; i += 8) {
        float pre = s_u[i];
        __half2 g2 = *(const __half2*)(g_G + (size_t)i * NP + col);
        float2 g = __half22float2(g2);
        lse_step(g.x, pre, m0, s0);
        lse_step(g.y, pre, m1, s1);
    }
    rm[ty][tx * 2] = m0; rs[ty][tx * 2] = s0;
    rm[ty][tx * 2 + 1] = m1; rs[ty][tx * 2 + 1] = s1;
    __syncthreads();
    if (ty < 2) {
        int c = ty * 32 + tx;
        float M = rm[0][c], S = rs[0][c];
        #pragma unroll
        for (int r = 1; r < 8; r++) {
            float mo = rm[r][c], so = rs[r][c];
            float nm = fmaxf(M, mo);
            S = S * __expf(M - nm) + so * __expf(mo - nm);
            M = nm;
        }
        lvout[blockIdx.x * 64 + c] = -(M + __logf(S));
    }
}

// ---------------- 6) final: sum clip(exp(lu+logK+lv),0,1)*C ---------------------
__global__ __launch_bounds__(256) void final_kernel(const float* __restrict__ lu,
                                                    const float* __restrict__ lv) {
    __shared__ float s_v[NP];
    int tid = threadIdx.x;
    for (int j = tid * 4; j < NP; j += 1024)
        *(float4*)(s_v + j) = *(const float4*)(lv + j);
    __syncthreads();
    int warp = tid >> 5, lane = tid & 31;
    #pragma unroll
    for (int rr = 0; rr < 2; rr++) {
        int i = blockIdx.x * 16 + warp * 2 + rr;
        float pre = lu[i];
        const __half* row = g_G + (size_t)i * NP;
        float acc = 0.f;
        for (int jb = lane * 8; jb < NP; jb += 256) {
            uint4 pk = *(const uint4*)(row + jb);
            float4 l0 = *(const float4*)(s_v + jb);
            float4 l1 = *(const float4*)(s_v + jb + 4);
            const __half2* hh = (const __half2*)&pk;
            float gs[8];
            float2 t;
            t = __half22float2(hh[0]); gs[0] = t.x; gs[1] = t.y;
            t = __half22float2(hh[1]); gs[2] = t.x; gs[3] = t.y;
            t = __half22float2(hh[2]); gs[4] = t.x; gs[5] = t.y;
            t = __half22float2(hh[3]); gs[6] = t.x; gs[7] = t.y;
            float ls[8] = {l0.x, l0.y, l0.z, l0.w, l1.x, l1.y, l1.z, l1.w};
            #pragma unroll
            for (int q = 0; q < 8; q++) {
                float ch = fmaxf(1.f - gs[q], 0.f);           // C/2
                float lp = pre + fmaf(-10.f, ch, ls[q]);      // lu + logK + lv
                float p = fminf(__expf(lp), 1.f);
                acc = fmaf(p, 2.f * ch, acc);
            }
        }
        #pragma unroll
        for (int o = 16; o; o >>= 1) acc += __shfl_xor_sync(0xffffffffu, acc, o);
        if (lane == 0) g_part[i] = acc;
    }
}

// ---------------- 7) reduce + fallback + output ---------------------------------
__global__ __launch_bounds__(256) void reduce_kernel(float* __restrict__ out) {
    __shared__ double sd[256], sg[256];
    int tid = threadIdx.x;
    double a = 0.0, d = 0.0;
    for (int i = tid; i < NP; i += 256) {
        a += (double)g_part[i];
        d += (double)__half2float(g_G[(size_t)i * (NP + 1)]);  // diag: x_i . y_i
    }
    sd[tid] = a; sg[tid] = d;
    __syncthreads();
    for (int o = 128; o; o >>= 1) {
        if (tid < o) { sd[tid] += sd[tid + o]; sg[tid] += sg[tid + o]; }
        __syncthreads();
    }
    if (tid == 0) {
        float dist = (float)(sd[0] / (double)NP);
        float fb = (float)(1.0 - sg[0] / (double)NP);
        out[0] = (isnan(dist) || isinf(dist)) ? fb : dist;
    }
}

// ---------------- launch ---------------------------------------------------------
extern "C" void kernel_launch(void* const* d_in, const int* in_sizes, int n_in,
                              void* d_out, int out_size) {
    const float* emb = (const float*)d_in[0];
    const float* tgt = (const float*)d_in[1];
    float* out = (float*)d_out;

    normalize_kernel<<<2 * NP, 128>>>(emb, tgt);
    gemm_kernel<<<dim3(NP / BN, NP / BM), 256>>>();

    init_kernel<<<8, 1024>>>();
    for (int it = 0; it < 10; it++) {
        row_lse_kernel<<<512, 256>>>(g_lv, g_lu);
        col_lse_kernel<<<128, dim3(32, 8)>>>(g_lu, g_lv);
    }
    final_kernel<<<512, 256>>>(g_lu, g_lv);
    reduce_kernel<<<1, 256>>>(out);
}

// round 6
// speedup vs baseline: 4.4000x; 4.4000x over previous
#include <cuda_runtime.h>
#include <cuda_bf16.h>
#include <cuda_fp16.h>
#include <cstdint>
#include <math.h>

#define NP 8192
#define DIM 512
#define LOG2E 1.4426950408889634f
#define N10L2E -14.426950408889634f   /* -10 * log2(e) */
#define LN2 0.6931471805599453f

// ---------------- device scratch ------------------------------------------------
__device__ __nv_bfloat16 g_Xh[(size_t)NP * DIM];
__device__ __nv_bfloat16 g_Yh[(size_t)NP * DIM];
__device__ __half        g_G[(size_t)NP * NP];    // 128 MB, G[i][j] = x_i . y_j
__device__ __half        g_GT[(size_t)NP * NP];   // 128 MB, transpose
__device__ float         g_lu[NP], g_lv[NP], g_part[NP];

// ---------------- helpers -------------------------------------------------------
__device__ __forceinline__ uint32_t smem_u32(const void* p) {
    uint32_t a;
    asm("{ .reg .u64 t; cvta.to.shared.u64 t, %1; cvt.u32.u64 %0, t; }" : "=r"(a) : "l"(p));
    return a;
}
__device__ __forceinline__ void cp16(uint32_t s, const void* g) {
    asm volatile("cp.async.cg.shared.global [%0], [%1], 16;" :: "r"(s), "l"(g));
}
__device__ __forceinline__ void ldsm4(uint32_t& r0, uint32_t& r1, uint32_t& r2,
                                      uint32_t& r3, uint32_t a) {
    asm volatile("ldmatrix.sync.aligned.m8n8.x4.shared.b16 {%0,%1,%2,%3}, [%4];"
                 : "=r"(r0), "=r"(r1), "=r"(r2), "=r"(r3) : "r"(a));
}
__device__ __forceinline__ void mma16816(float* d, const uint32_t* a, const uint32_t* b) {
    asm volatile(
        "mma.sync.aligned.m16n8k16.row.col.f32.bf16.bf16.f32 "
        "{%0,%1,%2,%3}, {%4,%5,%6,%7}, {%8,%9}, {%0,%1,%2,%3};"
        : "+f"(d[0]), "+f"(d[1]), "+f"(d[2]), "+f"(d[3])
        : "r"(a[0]), "r"(a[1]), "r"(a[2]), "r"(a[3]), "r"(b[0]), "r"(b[1]));
}
__device__ __forceinline__ float ex2f(float x) {
    float r; asm("ex2.approx.f32 %0, %1;" : "=f"(r) : "f"(x)); return r;
}
__device__ __forceinline__ float lg2f(float x) {
    float r; asm("lg2.approx.f32 %0, %1;" : "=f"(r) : "f"(x)); return r;
}

// ---------------- 1) normalize: fp32 -> unit rows -> bf16 ----------------------
__global__ __launch_bounds__(128) void normalize_kernel(const float* __restrict__ x,
                                                        const float* __restrict__ y) {
    int b = blockIdx.x;
    const float* src = (b < NP) ? x : y;
    __nv_bfloat16* dst = (b < NP) ? g_Xh : g_Yh;
    int i = (b < NP) ? b : b - NP;
    int tid = threadIdx.x;

    float4 v = ((const float4*)(src + (size_t)i * DIM))[tid];
    float ss = v.x * v.x + v.y * v.y + v.z * v.z + v.w * v.w;
    __shared__ float red[128];
    red[tid] = ss;
    __syncthreads();
    for (int o = 64; o; o >>= 1) {
        if (tid < o) red[tid] += red[tid + o];
        __syncthreads();
    }
    float inv = 1.f / fmaxf(sqrtf(red[0]), 1e-12f);
    __nv_bfloat162* d2 = (__nv_bfloat162*)(dst + (size_t)i * DIM);
    d2[tid * 2]     = __floats2bfloat162_rn(v.x * inv, v.y * inv);
    d2[tid * 2 + 1] = __floats2bfloat162_rn(v.z * inv, v.w * inv);
}

// ---------------- 2) HMMA bf16 GEMM: G = Xh * Yh^T, writes G and G^T -----------
#define BM 128
#define BN 64
#define BK 64
#define KITERS (DIM / BK)   // 8

__global__ __launch_bounds__(256) void gemm_kernel() {
    __shared__ __align__(1024) char sm[49152];
    uint32_t smb = smem_u32(sm);

    int tid = threadIdx.x;
    int lane = tid & 31;
    int w = tid >> 5;
    int warp_m = w & 3;        // 4 warps in M (32 rows each)
    int warp_n = w >> 2;       // 2 warps in N (32 cols each)
    int m0 = blockIdx.y * BM;
    int n0 = blockIdx.x * BN;

    auto load_stage = [&](int s, int kc) {
        #pragma unroll
        for (int it = 0; it < 4; it++) {
            int idx = tid + it * 256;
            int row = idx >> 3, ch = idx & 7;
            const char* g = (const char*)(g_Xh + (size_t)(m0 + row) * DIM + kc) + ch * 16;
            cp16(smb + s * 16384 + row * 128 + ((ch ^ (row & 7)) << 4), g);
        }
        #pragma unroll
        for (int it = 0; it < 2; it++) {
            int idx = tid + it * 256;
            int row = idx >> 3, ch = idx & 7;
            const char* g = (const char*)(g_Yh + (size_t)(n0 + row) * DIM + kc) + ch * 16;
            cp16(smb + 32768 + s * 8192 + row * 128 + ((ch ^ (row & 7)) << 4), g);
        }
        asm volatile("cp.async.commit_group;" ::: "memory");
    };

    float acc[2][4][4];
    #pragma unroll
    for (int mt = 0; mt < 2; mt++)
        #pragma unroll
        for (int nt = 0; nt < 4; nt++)
            #pragma unroll
            for (int q = 0; q < 4; q++) acc[mt][nt][q] = 0.f;

    load_stage(0, 0);
    load_stage(1, BK);

    for (int t = 0; t < KITERS; t++) {
        if (t < KITERS - 2)
            asm volatile("cp.async.wait_group 1;" ::: "memory");
        else
            asm volatile("cp.async.wait_group 0;" ::: "memory");
        __syncthreads();

        int s = t & 1;
        uint32_t aBase = smb + s * 16384;
        uint32_t bBase = smb + 32768 + s * 8192;

        #pragma unroll
        for (int ks = 0; ks < 4; ks++) {
            uint32_t afr[2][4], bfr[4][2];
            #pragma unroll
            for (int mt = 0; mt < 2; mt++) {
                int row = warp_m * 32 + mt * 16 + (lane & 15);
                int ch = ks * 2 + (lane >> 4);
                ldsm4(afr[mt][0], afr[mt][1], afr[mt][2], afr[mt][3],
                      aBase + row * 128 + ((ch ^ (row & 7)) << 4));
            }
            #pragma unroll
            for (int nt2 = 0; nt2 < 2; nt2++) {
                int row = warp_n * 32 + nt2 * 16 + (lane & 15);
                int ch = ks * 2 + (lane >> 4);
                uint32_t r0, r1, r2, r3;
                ldsm4(r0, r1, r2, r3, bBase + row * 128 + ((ch ^ (row & 7)) << 4));
                bfr[nt2 * 2][0] = r0;     bfr[nt2 * 2][1] = r2;
                bfr[nt2 * 2 + 1][0] = r1; bfr[nt2 * 2 + 1][1] = r3;
            }
            #pragma unroll
            for (int mt = 0; mt < 2; mt++)
                #pragma unroll
                for (int nt = 0; nt < 4; nt++)
                    mma16816(acc[mt][nt], afr[mt], bfr[nt]);
        }
        __syncthreads();
        if (t + 2 < KITERS) load_stage(s, (t + 2) * BK);
    }

    // ---- epilogue: stage tile in BOTH layouts, then coalesced dual store ----
    // stA: [128][68] halves (pitch 68 -> 4B-aligned rows, low smem conflicts)
    // stB: [64][132] halves (transposed tile)
    __half* stA = (__half*)sm;
    __half* stB = (__half*)(sm + 17408);
    #pragma unroll
    for (int mt = 0; mt < 2; mt++)
        #pragma unroll
        for (int nt = 0; nt < 4; nt++) {
            int lr = warp_m * 32 + mt * 16 + (lane >> 2);
            int lc = warp_n * 32 + nt * 8 + (lane & 3) * 2;
            __half2 h0 = __floats2half2_rn(acc[mt][nt][0], acc[mt][nt][1]);
            __half2 h1 = __floats2half2_rn(acc[mt][nt][2], acc[mt][nt][3]);
            *(__half2*)(stA + lr * 68 + lc) = h0;
            *(__half2*)(stA + (lr + 8) * 68 + lc) = h1;
            stB[lc * 132 + lr] = __low2half(h0);
            stB[(lc + 1) * 132 + lr] = __high2half(h0);
            stB[lc * 132 + lr + 8] = __low2half(h1);
            stB[(lc + 1) * 132 + lr + 8] = __high2half(h1);
        }
    __syncthreads();
    {   // G: 128 rows x 2 segs x 64B
        int lr = tid >> 1, seg = tid & 1;
        const uint* src = (const uint*)(stA + lr * 68) + seg * 16;
        uint* dst = (uint*)(g_G + (size_t)(m0 + lr) * NP + n0) + seg * 16;
        #pragma unroll
        for (int q = 0; q < 16; q++) dst[q] = src[q];
    }
    {   // GT: 64 rows x 4 segs x 64B
        int c = tid >> 2, seg = tid & 3;
        const uint* src = (const uint*)(stB + c * 132) + seg * 16;
        uint* dst = (uint*)(g_GT + (size_t)(n0 + c) * NP + m0) + seg * 16;
        #pragma unroll
        for (int q = 0; q < 16; q++) dst[q] = src[q];
    }
}

// ---------------- 3) init potentials -------------------------------------------
__global__ void init_kernel() {
    int i = blockIdx.x * blockDim.x + threadIdx.x;
    if (i < NP) { g_lu[i] = 0.f; g_lv[i] = 0.f; }
}

// ---------------- 4) branch-free streaming LSE pass -----------------------------
// tout[i] = -( M + ln( sum_j 2^( -10*log2e*c_ij + (tin_j - M)*log2e ) ) )
// M = max_j tin_j is a valid stabilizer since logK <= 0; underflow -> 0 is exact.
__global__ __launch_bounds__(256) void lse_pass(int useT,
                                                const float* __restrict__ tin,
                                                float* __restrict__ tout) {
    const __half* Gm = useT ? g_GT : g_G;
    __shared__ float s_t[NP];
    __shared__ float s_red[8];
    int tid = threadIdx.x;

    float mloc = -1e30f;
    for (int j = tid * 4; j < NP; j += 1024) {
        float4 v = *(const float4*)(tin + j);
        *(float4*)(s_t + j) = v;
        mloc = fmaxf(fmaxf(mloc, fmaxf(v.x, v.y)), fmaxf(v.z, v.w));
    }
    #pragma unroll
    for (int o = 16; o; o >>= 1) mloc = fmaxf(mloc, __shfl_xor_sync(0xffffffffu, mloc, o));
    if ((tid & 31) == 0) s_red[tid >> 5] = mloc;
    __syncthreads();
    float M = s_red[0];
    #pragma unroll
    for (int k = 1; k < 8; k++) M = fmaxf(M, s_red[k]);
    for (int j = tid * 4; j < NP; j += 1024) {
        float4 v = *(float4*)(s_t + j);
        v.x = (v.x - M) * LOG2E; v.y = (v.y - M) * LOG2E;
        v.z = (v.z - M) * LOG2E; v.w = (v.w - M) * LOG2E;
        *(float4*)(s_t + j) = v;
    }
    __syncthreads();

    int warp = tid >> 5, lane = tid & 31;
    int i0 = blockIdx.x * 16 + warp * 2;
    const uint4* r0 = (const uint4*)(Gm + (size_t)i0 * NP);
    const uint4* r1 = (const uint4*)(Gm + (size_t)(i0 + 1) * NP);
    const __half2 one2 = __floats2half2_rn(1.f, 1.f);
    const __half2 zero2 = __floats2half2_rn(0.f, 0.f);

    float sA = 0.f, sB = 0.f, sC = 0.f, sD = 0.f;
    #pragma unroll 2
    for (int jb = lane; jb < NP / 8; jb += 32) {
        uint4 p0 = __ldcs(r0 + jb);
        uint4 p1 = __ldcs(r1 + jb);
        float tv[8];
        *(float4*)(tv) = *(const float4*)(s_t + jb * 8);
        *(float4*)(tv + 4) = *(const float4*)(s_t + jb * 8 + 4);
        const __half2* h0 = (const __half2*)&p0;
        const __half2* h1 = (const __half2*)&p1;
        #pragma unroll
        for (int q = 0; q < 4; q++) {
            float2 c0 = __half22float2(__hmax2(__hsub2(one2, h0[q]), zero2));
            float2 c1 = __half22float2(__hmax2(__hsub2(one2, h1[q]), zero2));
            sA += ex2f(fmaf(N10L2E, c0.x, tv[2 * q]));
            sB += ex2f(fmaf(N10L2E, c0.y, tv[2 * q + 1]));
            sC += ex2f(fmaf(N10L2E, c1.x, tv[2 * q]));
            sD += ex2f(fmaf(N10L2E, c1.y, tv[2 * q + 1]));
        }
    }
    float s0 = sA + sB, s1 = sC + sD;
    #pragma unroll
    for (int o = 16; o; o >>= 1) {
        s0 += __shfl_xor_sync(0xffffffffu, s0, o);
        s1 += __shfl_xor_sync(0xffffffffu, s1, o);
    }
    if (lane == 0) {
        tout[i0]     = -(M + LN2 * lg2f(s0));
        tout[i0 + 1] = -(M + LN2 * lg2f(s1));
    }
}

// ---------------- 5) final: sum clip(exp(lu+logK+lv),0,1)*C ---------------------
__global__ __launch_bounds__(256) void final_kernel(const float* __restrict__ lu,
                                                    const float* __restrict__ lv) {
    __shared__ float s_t[NP];
    int tid = threadIdx.x;
    for (int j = tid * 4; j < NP; j += 1024) {
        float4 v = *(const float4*)(lv + j);
        v.x *= LOG2E; v.y *= LOG2E; v.z *= LOG2E; v.w *= LOG2E;
        *(float4*)(s_t + j) = v;
    }
    __syncthreads();

    int warp = tid >> 5, lane = tid & 31;
    int i0 = blockIdx.x * 16 + warp * 2;
    float pre0 = lu[i0] * LOG2E;
    float pre1 = lu[i0 + 1] * LOG2E;
    const uint4* r0 = (const uint4*)(g_G + (size_t)i0 * NP);
    const uint4* r1 = (const uint4*)(g_G + (size_t)(i0 + 1) * NP);
    const __half2 one2 = __floats2half2_rn(1.f, 1.f);
    const __half2 zero2 = __floats2half2_rn(0.f, 0.f);

    float a0 = 0.f, a1 = 0.f;
    #pragma unroll 2
    for (int jb = lane; jb < NP / 8; jb += 32) {
        uint4 p0 = __ldcs(r0 + jb);
        uint4 p1 = __ldcs(r1 + jb);
        float tv[8];
        *(float4*)(tv) = *(const float4*)(s_t + jb * 8);
        *(float4*)(tv + 4) = *(const float4*)(s_t + jb * 8 + 4);
        const __half2* h0 = (const __half2*)&p0;
        const __half2* h1 = (const __half2*)&p1;
        #pragma unroll
        for (int q = 0; q < 4; q++) {
            float2 c0 = __half22float2(__hmax2(__hsub2(one2, h0[q]), zero2));
            float2 c1 = __half22float2(__hmax2(__hsub2(one2, h1[q]), zero2));
            float e;
            e = fminf(ex2f(fmaf(N10L2E, c0.x, pre0 + tv[2 * q])), 1.f);     a0 = fmaf(e, c0.x, a0);
            e = fminf(ex2f(fmaf(N10L2E, c0.y, pre0 + tv[2 * q + 1])), 1.f); a0 = fmaf(e, c0.y, a0);
            e = fminf(ex2f(fmaf(N10L2E, c1.x, pre1 + tv[2 * q])), 1.f);     a1 = fmaf(e, c1.x, a1);
            e = fminf(ex2f(fmaf(N10L2E, c1.y, pre1 + tv[2 * q + 1])), 1.f); a1 = fmaf(e, c1.y, a1);
        }
    }
    #pragma unroll
    for (int o = 16; o; o >>= 1) {
        a0 += __shfl_xor_sync(0xffffffffu, a0, o);
        a1 += __shfl_xor_sync(0xffffffffu, a1, o);
    }
    if (lane == 0) {
        g_part[i0]     = 2.f * a0;   // C = 2*c
        g_part[i0 + 1] = 2.f * a1;
    }
}

// ---------------- 6) reduce + fallback + output ---------------------------------
__global__ __launch_bounds__(256) void reduce_kernel(float* __restrict__ out) {
    __shared__ double sd[256], sg[256];
    int tid = threadIdx.x;
    double a = 0.0, d = 0.0;
    for (int i = tid; i < NP; i += 256) {
        a += (double)g_part[i];
        d += (double)__half2float(g_G[(size_t)i * (NP + 1)]);  // diag: x_i . y_i
    }
    sd[tid] = a; sg[tid] = d;
    __syncthreads();
    for (int o = 128; o; o >>= 1) {
        if (tid < o) { sd[tid] += sd[tid + o]; sg[tid] += sg[tid + o]; }
        __syncthreads();
    }
    if (tid == 0) {
        float dist = (float)(sd[0] / (double)NP);
        float fb = (float)(1.0 - sg[0] / (double)NP);
        out[0] = (isnan(dist) || isinf(dist)) ? fb : dist;
    }
}

// ---------------- launch ---------------------------------------------------------
extern "C" void kernel_launch(void* const* d_in, const int* in_sizes, int n_in,
                              void* d_out, int out_size) {
    const float* emb = (const float*)d_in[0];
    const float* tgt = (const float*)d_in[1];
    float* out = (float*)d_out;

    normalize_kernel<<<2 * NP, 128>>>(emb, tgt);
    gemm_kernel<<<dim3(NP / BN, NP / BM), 256>>>();

    init_kernel<<<8, 1024>>>();
    for (int it = 0; it < 10; it++) {
        lse_pass<<<512, 256>>>(0, g_lv, g_lu);   // row update: G rows
        lse_pass<<<512, 256>>>(1, g_lu, g_lv);   // col update: G^T rows
    }
    final_kernel<<<512, 256>>>(g_lu, g_lv);
    reduce_kernel<<<1, 256>>>(out);
}